// round 6
// baseline (speedup 1.0000x reference)
#include <cuda_runtime.h>
#include <cstdint>

#define BATCH   8192
#define BOX     10
#define PAIR    90          // BOX*(BOX-1)
#define NUM_OT  151
#define NUM_QT  65
// out elements = 65*90*151*151 = 133,385,850

// ---------------------------------------------------------------------------
// Scatter-add kernel, restructured for memory-level parallelism:
// one thread per (batch, i) row -> 9 independent atomicAdds per thread.
// 8192*10 = 81,920 threads. Each thread's 9 REDG ops are independent,
// hiding the ~318-cycle global-atomic latency.
// ---------------------------------------------------------------------------
__global__ void __launch_bounds__(256)
scatter_row_kernel(const int*   __restrict__ obj_label,  // [BATCH, BOX]
                   const int*   __restrict__ qus_type,   // [BATCH]
                   const float* __restrict__ attention,  // [BATCH, BOX]
                   float*       __restrict__ out)        // [NUM_QT, PAIR, NUM_OT, NUM_OT]
{
    int t = blockIdx.x * blockDim.x + threadIdx.x;
    if (t >= BATCH * BOX) return;

    int b = t / BOX;
    int i = t - b * BOX;

    const int*   lab = obj_label + b * BOX;
    const float* att = attention + b * BOX;

    int   qt   = __ldg(qus_type + b);
    int   ol2  = __ldg(lab + i);           // obj_label[b, i]
    float atti = __ldg(att + i);           // attention[b, i]

    // Base offset for (qt, p=i*9) slice group, plus the fixed ol2 column.
    // idx(p) = ((qt*PAIR + p)*NUM_OT + ol1)*NUM_OT + ol2
    size_t base = ((size_t)qt * PAIR + (size_t)i * (BOX - 1)) * (NUM_OT * NUM_OT)
                  + (size_t)ol2;

    #pragma unroll
    for (int jj = 0; jj < BOX - 1; jj++) {
        int j = jj + (jj >= i ? 1 : 0);    // all j != i, ascending
        int   ol1 = __ldg(lab + j);
        float val = __ldg(att + j) * atti;
        size_t idx = base + (size_t)jj * (NUM_OT * NUM_OT) + (size_t)ol1 * NUM_OT;
        atomicAdd(out + idx, val);         // 9 independent REDGs in flight
    }
}

// ---------------------------------------------------------------------------
// Launch: driver-optimized D2D memcpy for the bulk, then scatter (same
// stream -> ordered). Both are graph-capturable.
// ---------------------------------------------------------------------------
extern "C" void kernel_launch(void* const* d_in, const int* in_sizes, int n_in,
                              void* d_out, int out_size)
{
    const int*   obj_label    = (const int*)  d_in[0]; // [8192,10] int32
    const int*   qus_type     = (const int*)  d_in[1]; // [8192]    int32
    const float* attention    = (const float*)d_in[2]; // [8192,10] float32
    const float* score_matrix = (const float*)d_in[3]; // [65,90,151,151] float32
    float*       out          = (float*)d_out;

    // Bulk copy: let the driver's tuned copy path saturate HBM.
    cudaMemcpyAsync(out, score_matrix, (size_t)out_size * sizeof(float),
                    cudaMemcpyDeviceToDevice, 0);

    // Scatter-add (default stream -> ordered after the copy).
    {
        int total   = BATCH * BOX;               // 81,920
        int threads = 256;
        int blocks  = (total + threads - 1) / threads;
        scatter_row_kernel<<<blocks, threads>>>(obj_label, qus_type, attention, out);
    }
}

// round 8
// speedup vs baseline: 1.8117x; 1.8117x over previous
#include <cuda_runtime.h>
#include <cstdint>

#define BATCH   8192
#define BOX     10
#define PAIR    90          // BOX*(BOX-1)
#define NUM_OT  151
#define NUM_QT  65
#define SLICE   (NUM_OT * NUM_OT)   // 22801 floats per (qt, pair) slice

// ---------------- device scratch (static, no allocation) -------------------
__device__ int                g_bucket_start[NUM_QT + 1];
__device__ int                g_slot[BATCH];
__device__ unsigned long long g_pair_data[(size_t)PAIR * BATCH];  // 5.9 MB

// ---------------------------------------------------------------------------
// K1: bucket batches by qus_type. Single block.
// ---------------------------------------------------------------------------
__global__ void bucket_kernel(const int* __restrict__ qus_type)
{
    __shared__ int s_count[NUM_QT];
    __shared__ int s_cursor[NUM_QT];
    int tid = threadIdx.x;

    if (tid < NUM_QT) s_count[tid] = 0;
    __syncthreads();

    for (int b = tid; b < BATCH; b += blockDim.x)
        atomicAdd(&s_count[__ldg(qus_type + b)], 1);
    __syncthreads();

    if (tid == 0) {
        int acc = 0;
        for (int q = 0; q < NUM_QT; q++) {
            g_bucket_start[q] = acc;
            s_cursor[q] = acc;
            acc += s_count[q];
        }
        g_bucket_start[NUM_QT] = acc;   // == BATCH
    }
    __syncthreads();

    for (int b = tid; b < BATCH; b += blockDim.x) {
        int qt = __ldg(qus_type + b);
        g_slot[b] = atomicAdd(&s_cursor[qt], 1);
    }
}

// ---------------------------------------------------------------------------
// K2: precompute packed {offset, value} per (batch, pair), grouped so that
// each (qt, p) slice's entries are contiguous: pair_data[p*BATCH + slot].
// ---------------------------------------------------------------------------
__global__ void __launch_bounds__(256)
pairdata_kernel(const int*   __restrict__ obj_label,   // [BATCH, BOX]
                const float* __restrict__ attention)   // [BATCH, BOX]
{
    int t = blockIdx.x * blockDim.x + threadIdx.x;
    if (t >= BATCH * PAIR) return;

    int b = t / PAIR;
    int p = t - b * PAIR;

    int i  = p / (BOX - 1);
    int jj = p - i * (BOX - 1);
    int j  = jj + (jj >= i ? 1 : 0);

    int   ol1 = __ldg(obj_label + b * BOX + j);
    int   ol2 = __ldg(obj_label + b * BOX + i);
    float val = __ldg(attention + b * BOX + j) * __ldg(attention + b * BOX + i);

    unsigned int off = (unsigned)(ol1 * NUM_OT + ol2);
    unsigned long long packed =
        ((unsigned long long)off << 32) | (unsigned long long)__float_as_uint(val);

    g_pair_data[(size_t)p * BATCH + g_slot[b]] = packed;
}

// ---------------------------------------------------------------------------
// K3: fused copy + scatter. One block per output slice (qt, p).
//  Phase 1: stream-copy the 91KB slice (loads evict-first, stores L2-cached
//           so the following atomics hit resident lines).
//  Phase 2: apply this slice's ~126 precomputed adds (contiguous reads).
// ---------------------------------------------------------------------------
__global__ void __launch_bounds__(256)
fused_kernel(const float* __restrict__ src,
             float*       __restrict__ out)
{
    const int slice = blockIdx.x;            // 0 .. 5849
    const int qt    = slice / PAIR;
    const int p     = slice - qt * PAIR;
    const size_t base = (size_t)slice * SLICE;

    const float* s = src + base;
    float*       d = out + base;

    // ---- Phase 1: copy 22801 floats with 16B-aligned vector body ----
    const int head = (4 - (int)(base & 3)) & 3;
    if (threadIdx.x < head)
        __stcg(d + threadIdx.x, __ldcs(s + threadIdx.x));

    const int n4 = (SLICE - head) >> 2;
    const float4* __restrict__ s4 = (const float4*)(s + head);
    float4*       __restrict__ d4 = (float4*)(d + head);
    #pragma unroll 4
    for (int i = threadIdx.x; i < n4; i += 256)
        __stcg(d4 + i, __ldcs(s4 + i));

    const int tail_start = head + (n4 << 2);
    const int tail = SLICE - tail_start;     // 0..3
    if (threadIdx.x < tail)
        __stcg(d + tail_start + threadIdx.x, __ldcs(s + tail_start + threadIdx.x));

    __syncthreads();

    // ---- Phase 2: scatter-adds for this slice (targets are L2-hot) ----
    const int start = g_bucket_start[qt];
    const int end   = g_bucket_start[qt + 1];
    const unsigned long long* __restrict__ pd = g_pair_data + (size_t)p * BATCH;

    for (int sI = start + (int)threadIdx.x; sI < end; sI += 256) {
        unsigned long long e = __ldg(pd + sI);
        atomicAdd(d + (unsigned)(e >> 32), __uint_as_float((unsigned)e));
    }
}

// ---------------------------------------------------------------------------
// Launch: K1 -> K2 -> K3, same stream (ordered), all graph-capturable.
// ---------------------------------------------------------------------------
extern "C" void kernel_launch(void* const* d_in, const int* in_sizes, int n_in,
                              void* d_out, int out_size)
{
    const int*   obj_label    = (const int*)  d_in[0]; // [8192,10] int32
    const int*   qus_type     = (const int*)  d_in[1]; // [8192]    int32
    const float* attention    = (const float*)d_in[2]; // [8192,10] float32
    const float* score_matrix = (const float*)d_in[3]; // [65,90,151,151] float32
    float*       out          = (float*)d_out;

    bucket_kernel<<<1, 1024>>>(qus_type);

    {
        int total   = BATCH * PAIR;              // 737,280
        int blocks  = (total + 255) / 256;
        pairdata_kernel<<<blocks, 256>>>(obj_label, attention);
    }

    fused_kernel<<<NUM_QT * PAIR, 256>>>(score_matrix, out);
}